// round 10
// baseline (speedup 1.0000x reference)
#include <cuda_runtime.h>
#include <stdint.h>

#define HEADS   8
#define DHEAD   32
#define HS      48
#define WS      48
#define HWs     (HS * WS)          // 2304
#define WIN     7
#define RAD     3
#define KN      (WIN * WIN)        // 49
#define TILE    16                 // 16x16 pixel tile, 2 x-paired pixels per thread
#define NTHR    128
#define HALO    (TILE + 2 * RAD)   // 22
#define HPADW   48                 // row stride in floats: 4 warp rows tile banks exactly
#define HALO_PIX (HALO * HALO)     // 484

#define CHCH    8                  // channels per chunk
#define CH_PLANE (HALO * HPADW)    // 1056 floats per channel plane
#define CHUNK_F  (CHCH * CH_PLANE) // 8448 floats per buffer
#define SMEM_BYTES (3 * CHUNK_F * 4)   // 101376 B (3-buffer ring)

typedef unsigned long long ull;

__device__ __forceinline__ ull pack2(float lo, float hi) {
    ull r;
    asm("mov.b64 %0, {%1, %2};" : "=l"(r) : "f"(lo), "f"(hi));
    return r;
}
__device__ __forceinline__ void unpack2(ull v, float& lo, float& hi) {
    asm("mov.b64 {%0, %1}, %2;" : "=f"(lo), "=f"(hi) : "l"(v));
}
__device__ __forceinline__ void ffma2(ull& acc, ull a, ull b) {
    asm("fma.rn.f32x2 %0, %1, %2, %3;" : "=l"(acc) : "l"(a), "l"(b), "l"(acc));
}
__device__ __forceinline__ ull add2(ull a, ull b) {
    ull r;
    asm("add.rn.f32x2 %0, %1, %2;" : "=l"(r) : "l"(a), "l"(b));
    return r;
}
__device__ __forceinline__ void cp4(uint32_t dst, const float* src) {
    asm volatile("cp.async.ca.shared.global [%0], [%1], 4;" :: "r"(dst), "l"(src));
}
#define CP_COMMIT()  asm volatile("cp.async.commit_group;" ::: "memory")
#define CP_WAIT(N)   asm volatile("cp.async.wait_group %0;" :: "n"(N) : "memory")

// Issue one 8-channel scalar-plane halo chunk via cp.async (zero register residency).
__device__ __forceinline__ void load_chunk(const float* __restrict__ plane0,
                                           uint32_t sbase,
                                           int tid, int tileX0, int tileY0)
{
    #pragma unroll
    for (int ps = 0; ps < HALO_PIX; ps += NTHR) {
        const int p = ps + tid;
        if (p < HALO_PIX) {
            const int hy = p / HALO;
            const int hx = p - hy * HALO;
            const int gy = tileY0 + hy - RAD;
            const int gx = tileX0 + hx - RAD;
            const bool valid = (gy >= 0) & (gy < HS) & (gx >= 0) & (gx < WS);
            const uint32_t db = sbase + (uint32_t)(hy * HPADW + hx) * 4u;
            if (valid) {
                const float* sp = plane0 + gy * WS + gx;
                #pragma unroll
                for (int c = 0; c < CHCH; c++)
                    cp4(db + (uint32_t)c * (CH_PLANE * 4), sp + c * HWs);
            } else {
                #pragma unroll
                for (int c = 0; c < CHCH; c++) {
                    uint32_t a = db + (uint32_t)c * (CH_PLANE * 4);
                    asm volatile("st.shared.b32 [%0], %1;" :: "r"(a), "r"(0u));
                }
            }
        }
    }
    CP_COMMIT();
}

// Pass-1: accumulate packed (px0, px1) scores over one 8-channel chunk.
__device__ __forceinline__ void pass1_chunk(const float* __restrict__ buf,
                                            const float* __restrict__ qp, int cBase,
                                            ull* __restrict__ s,
                                            int tyW, int xoff, int pixB)
{
    ull qv[CHCH];
    #pragma unroll
    for (int j = 0; j < CHCH; j++) {
        float2 t = __ldg((const float2*)(qp + (cBase + j) * HWs + pixB));
        qv[j] = pack2(t.x, t.y);
    }
    #pragma unroll 1
    for (int c = 0; c < CHCH; c++) {
        const float* kb = buf + c * CH_PLANE + tyW * HPADW + xoff;
        const ull qc = qv[c];
        #pragma unroll
        for (int dy = 0; dy < WIN; dy++) {
            const ull* wr = (const ull*)(kb + dy * HPADW);
            ull L0 = wr[0], L1 = wr[1], L2 = wr[2], L3 = wr[3];
            float k0, k1, k2, k3, k4, k5, k6, k7;
            unpack2(L0, k0, k1);
            unpack2(L1, k2, k3);
            unpack2(L2, k4, k5);
            unpack2(L3, k6, k7);
            const int b = dy * WIN;
            ffma2(s[b + 0], qc, L0);
            ffma2(s[b + 1], qc, pack2(k1, k2));
            ffma2(s[b + 2], qc, L1);
            ffma2(s[b + 3], qc, pack2(k3, k4));
            ffma2(s[b + 4], qc, L2);
            ffma2(s[b + 5], qc, pack2(k5, k6));
            ffma2(s[b + 6], qc, L3);
        }
    }
}

// Pass-2: one 8-channel chunk -> packed (px0, px1) outputs.
__device__ __forceinline__ void vchunk(const float* __restrict__ buf,
                                       float* __restrict__ op, int cBase,
                                       const ull* __restrict__ s,
                                       int tyW, int xoff, int pixB)
{
    #pragma unroll 1
    for (int c = 0; c < CHCH; c++) {
        const float* vb = buf + c * CH_PLANE + tyW * HPADW + xoff;
        ull a0 = 0, a1 = 0, a2 = 0, a3 = 0;
        #pragma unroll
        for (int dy = 0; dy < WIN; dy++) {
            const ull* wr = (const ull*)(vb + dy * HPADW);
            ull L0 = wr[0], L1 = wr[1], L2 = wr[2], L3 = wr[3];
            float k0, k1, k2, k3, k4, k5, k6, k7;
            unpack2(L0, k0, k1);
            unpack2(L1, k2, k3);
            unpack2(L2, k4, k5);
            unpack2(L3, k6, k7);
            const int b = dy * WIN;
            ffma2(a0, s[b + 0], L0);
            ffma2(a1, s[b + 1], pack2(k1, k2));
            ffma2(a2, s[b + 2], L1);
            ffma2(a3, s[b + 3], pack2(k3, k4));
            ffma2(a0, s[b + 4], L2);
            ffma2(a1, s[b + 5], pack2(k5, k6));
            ffma2(a2, s[b + 6], L3);
        }
        ull tot = add2(add2(a0, a1), add2(a2, a3));
        float o0, o1;
        unpack2(tot, o0, o1);
        *(float2*)(op + (cBase + c) * HWs + pixB) = make_float2(o0, o1);
    }
}

__global__ __launch_bounds__(NTHR, 2)
void natten2d_kernel(const float* __restrict__ q,
                     const float* __restrict__ k,
                     const float* __restrict__ v,
                     float* __restrict__ out)
{
    extern __shared__ float sm[];
    float* buf0 = sm;
    float* buf1 = sm + 1 * CHUNK_F;
    float* buf2 = sm + 2 * CHUNK_F;
    const uint32_t sb0 = (uint32_t)__cvta_generic_to_shared(buf0);
    const uint32_t sb1 = (uint32_t)__cvta_generic_to_shared(buf1);
    const uint32_t sb2 = (uint32_t)__cvta_generic_to_shared(buf2);

    const int tid  = threadIdx.x;
    const int xoff = 2 * (tid & 7);        // even x offset -> 8-B aligned LDS.64/LDG.64
    const int tyW  = tid >> 3;             // 0..15

    const int tileX0 = blockIdx.x * TILE;
    const int tileY0 = blockIdx.y * TILE;
    const size_t base = (size_t)blockIdx.z * DHEAD * HWs;

    const float* qp = q + base;
    const float* kp = k + base;
    const float* vp = v + base;
    float* op = out + base;

    const int x    = tileX0 + xoff;        // px0; px1 = x+1
    const int y    = tileY0 + tyW;
    const int pixB = y * WS + x;

    // ---- issue K0..K2 ----
    load_chunk(kp,            sb0, tid, tileX0, tileY0);
    load_chunk(kp +  8 * HWs, sb1, tid, tileX0, tileY0);
    load_chunk(kp + 16 * HWs, sb2, tid, tileX0, tileY0);

    ull s[KN];
    #pragma unroll
    for (int n = 0; n < KN; n++) s[n] = 0ULL;

    CP_WAIT(2); __syncthreads();                        // K0 ready
    pass1_chunk(buf0, qp, 0, s, tyW, xoff, pixB);

    CP_WAIT(1); __syncthreads();                        // K1 ready, buf0 free
    load_chunk(kp + 24 * HWs, sb0, tid, tileX0, tileY0);   // K3
    pass1_chunk(buf1, qp, 8, s, tyW, xoff, pixB);

    CP_WAIT(1); __syncthreads();                        // K2 ready, buf1 free
    load_chunk(vp,            sb1, tid, tileX0, tileY0);   // V0
    pass1_chunk(buf2, qp, 16, s, tyW, xoff, pixB);

    CP_WAIT(1); __syncthreads();                        // K3 ready, buf2 free
    load_chunk(vp +  8 * HWs, sb2, tid, tileX0, tileY0);   // V1
    pass1_chunk(buf0, qp, 24, s, tyW, xoff, pixB);

    // ---- mask + scale + softmax on packed (px0, px1) scores ----
    {
        const float scale = 0.17677669529663687f; // 1/sqrt(32)
        float p0s[KN], p1s[KN];
        float m0 = -1e30f, m1 = -1e30f;
        #pragma unroll
        for (int n = 0; n < KN; n++) {
            float lo, hi;
            unpack2(s[n], lo, hi);
            const int dy = n / WIN - RAD;
            const int dx = n % WIN - RAD;
            const int gy  = y + dy;
            const int gx0 = x + dx;
            const int gx1 = gx0 + 1;
            const bool vy  = (gy >= 0) & (gy < HS);
            const bool ok0 = vy & (gx0 >= 0) & (gx0 < WS);
            const bool ok1 = vy & (gx1 >= 0) & (gx1 < WS);
            p0s[n] = ok0 ? lo * scale : -1e30f;
            p1s[n] = ok1 ? hi * scale : -1e30f;
            m0 = fmaxf(m0, p0s[n]);
            m1 = fmaxf(m1, p1s[n]);
        }
        float sum0 = 0.0f, sum1 = 0.0f;
        #pragma unroll
        for (int n = 0; n < KN; n++) {
            p0s[n] = __expf(p0s[n] - m0);
            p1s[n] = __expf(p1s[n] - m1);
            sum0 += p0s[n];
            sum1 += p1s[n];
        }
        const float inv0 = 1.0f / sum0;
        const float inv1 = 1.0f / sum1;
        #pragma unroll
        for (int n = 0; n < KN; n++)
            s[n] = pack2(p0s[n] * inv0, p1s[n] * inv1);
    }

    // ---- pass 2 ----
    CP_WAIT(1); __syncthreads();                        // V0 ready, buf0 free
    load_chunk(vp + 16 * HWs, sb0, tid, tileX0, tileY0);   // V2
    vchunk(buf1, op, 0, s, tyW, xoff, pixB);

    CP_WAIT(1); __syncthreads();                        // V1 ready, buf1 free
    load_chunk(vp + 24 * HWs, sb1, tid, tileX0, tileY0);   // V3
    vchunk(buf2, op, 8, s, tyW, xoff, pixB);

    CP_WAIT(1); __syncthreads();                        // V2 ready
    vchunk(buf0, op, 16, s, tyW, xoff, pixB);

    CP_WAIT(0); __syncthreads();                        // V3 ready
    vchunk(buf1, op, 24, s, tyW, xoff, pixB);
}

extern "C" void kernel_launch(void* const* d_in, const int* in_sizes, int n_in,
                              void* d_out, int out_size)
{
    const float* q = (const float*)d_in[0];
    const float* k = (const float*)d_in[1];
    const float* v = (const float*)d_in[2];
    float* o = (float*)d_out;

    // Device-function attribute; graph-capture-safe, idempotent.
    cudaFuncSetAttribute(natten2d_kernel,
                         cudaFuncAttributeMaxDynamicSharedMemorySize, SMEM_BYTES);

    const int B = in_sizes[0] / (HEADS * DHEAD * HWs); // 4
    dim3 grid(WS / TILE, HS / TILE, B * HEADS);        // (3, 3, 32) = 288
    dim3 block(NTHR);                                  // 128 linear
    natten2d_kernel<<<grid, block, SMEM_BYTES>>>(q, k, v, o);
}